// round 1
// baseline (speedup 1.0000x reference)
#include <cuda_runtime.h>
#include <math.h>

#define NN 50000
#define EE 500000
#define FF 128
#define HH 128
#define OUTD 768

// ---------------- scratch (device globals: no allocation allowed) ----------------
__device__ float g_Q  [(size_t)NN * HH];    // Q (L1), Q2 (L2)
__device__ float g_nK [(size_t)NN * HH];    // node part of K linear
__device__ float g_nV [(size_t)NN * HH];    // node part of V linear
__device__ float g_eK [(size_t)EE * HH];    // per-edge K
__device__ float g_eV [(size_t)EE * HH];    // per-edge V
__device__ float g_den[(size_t)NN * HH];    // softmax denominators
__device__ float g_acc[(size_t)NN * HH];    // softmax-weighted V accumulators
__device__ float g_hn [(size_t)NN * HH];    // h_n / h_n1
__device__ float g_h  [(size_t)NN * HH];    // h (post-LN layer 1)
__device__ float g_lin[(size_t)NN * OUTD];  // pre-LN linear outputs (reused)
__device__ float g_h1 [(size_t)NN * OUTD];  // h1 (post-LN layer 2)
__device__ float g_gex[NN];                 // exp(gate logits)
__device__ float g_S[1];                    // sum of gate exps

// ---------------- generic segmented SGEMM ----------------
// C[M,N] = concat_k(A0,A1,A2) @ concat_k(B0,B1,B2) (+bias) (+gather row add)
// A segments: row-major [M, k_i] contiguous. B segments: pointer into weight,
// row stride = N (output cols == weight cols for every use here).
struct GemmP {
    const float* A0; const float* A1; const float* A2;
    int k0, k1, k2;
    const float* B0; const float* B1; const float* B2;
    const float* bias;     // [N] or null
    const int*   gidx;     // [M] or null
    const float* gsrc;     // [*, N] gathered row added to C
    float* C;
    int M, N;
};

__global__ __launch_bounds__(256) void sgemm128(GemmP p) {
    const int BM = 128, BN = 64, BK = 16;
    __shared__ float As[BK][BM + 4];
    __shared__ float Bs[BK][BN];
    int tid = threadIdx.x;
    int m0 = blockIdx.y * BM;
    int n0 = blockIdx.x * BN;
    int ty = tid >> 4;        // 0..15 (8-row group)
    int tx = tid & 15;        // 0..15 (4-col group)

    float acc[8][4];
#pragma unroll
    for (int i = 0; i < 8; i++)
#pragma unroll
        for (int j = 0; j < 4; j++) acc[i][j] = 0.f;

    int K = p.k0 + p.k1 + p.k2;
    int ar   = tid >> 2;        // 0..63
    int acol = (tid & 3) * 4;   // 0,4,8,12
    int br   = tid >> 4;        // 0..15
    int bc   = (tid & 15) * 4;  // 0..60

    for (int kb = 0; kb < K; kb += BK) {
        const float* A; const float* B; int lda; int ks;
        if (kb < p.k0)             { A = p.A0; B = p.B0; lda = p.k0; ks = kb; }
        else if (kb < p.k0 + p.k1) { A = p.A1; B = p.B1; lda = p.k1; ks = kb - p.k0; }
        else                       { A = p.A2; B = p.B2; lda = p.k2; ks = kb - p.k0 - p.k1; }

#pragma unroll
        for (int rr = 0; rr < 2; rr++) {
            int row = ar + rr * 64;
            int gm = m0 + row;
            float4 v = make_float4(0.f, 0.f, 0.f, 0.f);
            if (gm < p.M) v = *(const float4*)(A + (size_t)gm * lda + ks + acol);
            As[acol + 0][row] = v.x; As[acol + 1][row] = v.y;
            As[acol + 2][row] = v.z; As[acol + 3][row] = v.w;
        }
        {
            float4 bv = *(const float4*)(B + (size_t)(ks + br) * p.N + n0 + bc);
            *(float4*)&Bs[br][bc] = bv;
        }
        __syncthreads();
#pragma unroll
        for (int kk = 0; kk < BK; kk++) {
            float4 a0 = *(const float4*)&As[kk][ty * 8];
            float4 a1 = *(const float4*)&As[kk][ty * 8 + 4];
            float4 bb = *(const float4*)&Bs[kk][tx * 4];
            float a[8] = {a0.x, a0.y, a0.z, a0.w, a1.x, a1.y, a1.z, a1.w};
            float b[4] = {bb.x, bb.y, bb.z, bb.w};
#pragma unroll
            for (int i = 0; i < 8; i++)
#pragma unroll
                for (int j = 0; j < 4; j++)
                    acc[i][j] = fmaf(a[i], b[j], acc[i][j]);
        }
        __syncthreads();
    }

#pragma unroll
    for (int i = 0; i < 8; i++) {
        int gm = m0 + ty * 8 + i;
        if (gm >= p.M) continue;
        int gn = n0 + tx * 4;
        float4 r = make_float4(acc[i][0], acc[i][1], acc[i][2], acc[i][3]);
        if (p.bias) {
            float4 bb = *(const float4*)(p.bias + gn);
            r.x += bb.x; r.y += bb.y; r.z += bb.z; r.w += bb.w;
        }
        if (p.gsrc) {
            int gi = p.gidx[gm];
            float4 gg = *(const float4*)(p.gsrc + (size_t)gi * p.N + gn);
            r.x += gg.x; r.y += gg.y; r.z += gg.z; r.w += gg.w;
        }
        *(float4*)(p.C + (size_t)gm * p.N + gn) = r;
    }
}

// ---------------- edge attention scatter ----------------
// ex = exp(Q[dst]*eK); denom[dst]+=ex; accum[dst]+=ex*eV
__global__ __launch_bounds__(256) void edge_attn_k(
    const float* __restrict__ Q, const float* __restrict__ eK,
    const float* __restrict__ eV, const int* __restrict__ dst,
    float* __restrict__ den, float* __restrict__ acc)
{
    unsigned idx = blockIdx.x * 256u + threadIdx.x;
    if (idx >= (unsigned)EE * 32u) return;
    int e = idx >> 5;
    int c = (idx & 31) << 2;
    int d = dst[e];
    float4 q = *(const float4*)(Q  + (size_t)d * HH + c);
    float4 k = *(const float4*)(eK + (size_t)e * HH + c);
    float4 v = *(const float4*)(eV + (size_t)e * HH + c);
    float e0 = expf(q.x * k.x), e1 = expf(q.y * k.y);
    float e2 = expf(q.z * k.z), e3 = expf(q.w * k.w);
    float* dp = den + (size_t)d * HH + c;
    float* ap = acc + (size_t)d * HH + c;
    atomicAdd(dp + 0, e0); atomicAdd(dp + 1, e1);
    atomicAdd(dp + 2, e2); atomicAdd(dp + 3, e3);
    atomicAdd(ap + 0, e0 * v.x); atomicAdd(ap + 1, e1 * v.y);
    atomicAdd(ap + 2, e2 * v.z); atomicAdd(ap + 3, e3 * v.w);
}

__global__ __launch_bounds__(256) void node_div_k(
    const float* __restrict__ den, const float* __restrict__ acc,
    float* __restrict__ out)
{
    int i = blockIdx.x * 256 + threadIdx.x;
    if (i < NN * HH) {
        float d = den[i];
        out[i] = (d > 0.f) ? acc[i] / d : 0.f;
    }
}

// ---------------- layernorms ----------------
__global__ __launch_bounds__(128) void ln128_k(
    const float* __restrict__ x, const float* __restrict__ g,
    const float* __restrict__ b, float* __restrict__ y)
{
    int row = blockIdx.x, t = threadIdx.x;
    float v = x[(size_t)row * 128 + t];
    float s = v, s2 = v * v;
#pragma unroll
    for (int o = 16; o > 0; o >>= 1) {
        s  += __shfl_xor_sync(0xffffffffu, s, o);
        s2 += __shfl_xor_sync(0xffffffffu, s2, o);
    }
    __shared__ float ws[4], ws2[4];
    int w = t >> 5, l = t & 31;
    if (l == 0) { ws[w] = s; ws2[w] = s2; }
    __syncthreads();
    s  = ws[0] + ws[1] + ws[2] + ws[3];
    s2 = ws2[0] + ws2[1] + ws2[2] + ws2[3];
    float mu  = s * (1.f / 128.f);
    float var = s2 * (1.f / 128.f) - mu * mu;
    float r = rsqrtf(var + 1e-5f);
    y[(size_t)row * 128 + t] = (v - mu) * r * g[t] + b[t];
}

__global__ __launch_bounds__(256) void ln768_k(
    const float* __restrict__ x, const float* __restrict__ g,
    const float* __restrict__ b, float* __restrict__ y)
{
    int row = blockIdx.x, t = threadIdx.x;
    const float* xr = x + (size_t)row * 768;
    float v0 = xr[t], v1 = xr[t + 256], v2 = xr[t + 512];
    float s = v0 + v1 + v2;
    float s2 = v0 * v0 + v1 * v1 + v2 * v2;
#pragma unroll
    for (int o = 16; o > 0; o >>= 1) {
        s  += __shfl_xor_sync(0xffffffffu, s, o);
        s2 += __shfl_xor_sync(0xffffffffu, s2, o);
    }
    __shared__ float ws[8], ws2[8];
    int w = t >> 5, l = t & 31;
    if (l == 0) { ws[w] = s; ws2[w] = s2; }
    __syncthreads();
    s = 0.f; s2 = 0.f;
#pragma unroll
    for (int i = 0; i < 8; i++) { s += ws[i]; s2 += ws2[i]; }
    float mu  = s * (1.f / 768.f);
    float var = s2 * (1.f / 768.f) - mu * mu;
    float r = rsqrtf(var + 1e-5f);
    float* yr = y + (size_t)row * 768;
    yr[t]       = (v0 - mu) * r * g[t]       + b[t];
    yr[t + 256] = (v1 - mu) * r * g[t + 256] + b[t + 256];
    yr[t + 512] = (v2 - mu) * r * g[t + 512] + b[t + 512];
}

// ---------------- gate + pool ----------------
__global__ __launch_bounds__(256) void gate_k(
    const float* __restrict__ h1, const float* __restrict__ gw,
    const float* __restrict__ gb, float* __restrict__ gex,
    float* __restrict__ S)
{
    int w = threadIdx.x >> 5, l = threadIdx.x & 31;
    int node = blockIdx.x * 8 + w;
    float dot = 0.f;
    if (node < NN) {
        const float* hr = h1 + (size_t)node * 768;
#pragma unroll
        for (int k = 0; k < 24; k++)
            dot = fmaf(hr[l + 32 * k], gw[l + 32 * k], dot);
    }
#pragma unroll
    for (int o = 16; o > 0; o >>= 1) dot += __shfl_xor_sync(0xffffffffu, dot, o);
    __shared__ float ws[8];
    if (l == 0) {
        float ex = 0.f;
        if (node < NN) { ex = expf(dot + gb[0]); gex[node] = ex; }
        ws[w] = ex;
    }
    __syncthreads();
    if (threadIdx.x == 0) {
        float t = 0.f;
#pragma unroll
        for (int i = 0; i < 8; i++) t += ws[i];
        atomicAdd(S, t);
    }
}

__global__ __launch_bounds__(256) void pool_k(
    const float* __restrict__ h1, const float* __restrict__ gex,
    const float* __restrict__ S, float* __restrict__ out)
{
    int c = blockIdx.x * 256 + threadIdx.x;   // gridDim.x = 3 -> 768 cols
    int nstart = blockIdx.y * 512;
    int nend = nstart + 512; if (nend > NN) nend = NN;
    float a = 0.f;
    for (int n = nstart; n < nend; n++)
        a = fmaf(gex[n], h1[(size_t)n * 768 + c], a);
    atomicAdd(&out[c], a * (1.f / S[0]));
}

// ---------------- host ----------------
static void launch_gemm(const GemmP& p) {
    dim3 grid((p.N + 63) / 64, (p.M + 127) / 128);
    sgemm128<<<grid, 256>>>(p);
}

extern "C" void kernel_launch(void* const* d_in, const int* in_sizes, int n_in,
                              void* d_out, int out_size) {
    const float* kind   = (const float*)d_in[0];
    const float* edge_h = (const float*)d_in[1];
    const int*   src    = (const int*)  d_in[2];
    const int*   dst    = (const int*)  d_in[3];
    const float* KW  = (const float*)d_in[4];  const float* Kb  = (const float*)d_in[5];
    const float* VW  = (const float*)d_in[6];  const float* Vb  = (const float*)d_in[7];
    const float* QW  = (const float*)d_in[8];  const float* Qb  = (const float*)d_in[9];
    const float* WW  = (const float*)d_in[10]; const float* Wb  = (const float*)d_in[11];
    const float* K2W = (const float*)d_in[12]; const float* K2b = (const float*)d_in[13];
    const float* V2W = (const float*)d_in[14]; const float* V2b = (const float*)d_in[15];
    const float* Q2W = (const float*)d_in[16]; const float* Q2b = (const float*)d_in[17];
    const float* W2W = (const float*)d_in[18]; const float* W2b = (const float*)d_in[19];
    const float* ln1g = (const float*)d_in[20]; const float* ln1b = (const float*)d_in[21];
    const float* ln2g = (const float*)d_in[22]; const float* ln2b = (const float*)d_in[23];
    const float* gw  = (const float*)d_in[24]; const float* gb  = (const float*)d_in[25];
    float* out = (float*)d_out;

    static float *pQ = nullptr, *pnK, *pnV, *peK, *peV, *pden, *pacc,
                 *phn, *ph, *plin, *ph1, *pgex, *pS;
    if (!pQ) {
        cudaGetSymbolAddress((void**)&pQ,   g_Q);
        cudaGetSymbolAddress((void**)&pnK,  g_nK);
        cudaGetSymbolAddress((void**)&pnV,  g_nV);
        cudaGetSymbolAddress((void**)&peK,  g_eK);
        cudaGetSymbolAddress((void**)&peV,  g_eV);
        cudaGetSymbolAddress((void**)&pden, g_den);
        cudaGetSymbolAddress((void**)&pacc, g_acc);
        cudaGetSymbolAddress((void**)&phn,  g_hn);
        cudaGetSymbolAddress((void**)&ph,   g_h);
        cudaGetSymbolAddress((void**)&plin, g_lin);
        cudaGetSymbolAddress((void**)&ph1,  g_h1);
        cudaGetSymbolAddress((void**)&pgex, g_gex);
        cudaGetSymbolAddress((void**)&pS,   g_S);
    }

    const size_t nh_bytes = (size_t)NN * HH * sizeof(float);
    GemmP p;

    // ===================== layer 1 =====================
    cudaMemsetAsync(pden, 0, nh_bytes);
    cudaMemsetAsync(pacc, 0, nh_bytes);

    // Q = kind @ QW + Qb
    p = {kind, nullptr, nullptr, FF, 0, 0, QW, nullptr, nullptr,
         Qb, nullptr, nullptr, pQ, NN, HH};
    launch_gemm(p);
    // nodeK = kind @ KW[0:F] + Kb ; nodeV = kind @ VW[0:F] + Vb
    p = {kind, nullptr, nullptr, FF, 0, 0, KW, nullptr, nullptr,
         Kb, nullptr, nullptr, pnK, NN, HH};
    launch_gemm(p);
    p = {kind, nullptr, nullptr, FF, 0, 0, VW, nullptr, nullptr,
         Vb, nullptr, nullptr, pnV, NN, HH};
    launch_gemm(p);
    // eK = edge_h @ KW[F:2F] + nodeK[src]; eV likewise
    p = {edge_h, nullptr, nullptr, FF, 0, 0, KW + (size_t)FF * HH, nullptr, nullptr,
         nullptr, src, pnK, peK, EE, HH};
    launch_gemm(p);
    p = {edge_h, nullptr, nullptr, FF, 0, 0, VW + (size_t)FF * HH, nullptr, nullptr,
         nullptr, src, pnV, peV, EE, HH};
    launch_gemm(p);

    edge_attn_k<<<(EE * 32 + 255) / 256, 256>>>(pQ, peK, peV, dst, pden, pacc);
    node_div_k<<<(NN * HH + 255) / 256, 256>>>(pden, pacc, phn);

    // lin1 = concat(h_n, kind) @ WW + Wb ; h = LN(lin1)
    p = {phn, kind, nullptr, HH, FF, 0, WW, WW + (size_t)HH * HH, nullptr,
         Wb, nullptr, nullptr, plin, NN, HH};
    launch_gemm(p);
    ln128_k<<<NN, 128>>>(plin, ln1g, ln1b, ph);

    // ===================== layer 2 =====================
    cudaMemsetAsync(pden, 0, nh_bytes);
    cudaMemsetAsync(pacc, 0, nh_bytes);

    // Q2 = concat(kind, h) @ Q2W + Q2b
    p = {kind, ph, nullptr, FF, HH, 0, Q2W, Q2W + (size_t)FF * HH, nullptr,
         Q2b, nullptr, nullptr, pQ, NN, HH};
    launch_gemm(p);
    // nodeK2 = kind@K2W[0:F] + h@K2W[2F:3F] + K2b ; nodeV2 likewise
    p = {kind, ph, nullptr, FF, HH, 0, K2W, K2W + (size_t)2 * FF * HH, nullptr,
         K2b, nullptr, nullptr, pnK, NN, HH};
    launch_gemm(p);
    p = {kind, ph, nullptr, FF, HH, 0, V2W, V2W + (size_t)2 * FF * HH, nullptr,
         V2b, nullptr, nullptr, pnV, NN, HH};
    launch_gemm(p);
    // eK2 = edge_h @ K2W[F:2F] + nodeK2[src]; eV2 likewise
    p = {edge_h, nullptr, nullptr, FF, 0, 0, K2W + (size_t)FF * HH, nullptr, nullptr,
         nullptr, src, pnK, peK, EE, HH};
    launch_gemm(p);
    p = {edge_h, nullptr, nullptr, FF, 0, 0, V2W + (size_t)FF * HH, nullptr, nullptr,
         nullptr, src, pnV, peV, EE, HH};
    launch_gemm(p);

    edge_attn_k<<<(EE * 32 + 255) / 256, 256>>>(pQ, peK, peV, dst, pden, pacc);
    node_div_k<<<(NN * HH + 255) / 256, 256>>>(pden, pacc, phn);

    // lin2 = concat(h_n1, h, kind) @ W2W + W2b ; h1 = LN(lin2)
    p = {phn, ph, kind, HH, HH, FF, W2W, W2W + (size_t)HH * OUTD,
         W2W + (size_t)2 * HH * OUTD, W2b, nullptr, nullptr, plin, NN, OUTD};
    launch_gemm(p);
    ln768_k<<<NN, 256>>>(plin, ln2g, ln2b, ph1);

    // ===================== pooling =====================
    cudaMemsetAsync(pS, 0, sizeof(float));
    cudaMemsetAsync(out, 0, (size_t)OUTD * sizeof(float));
    gate_k<<<(NN + 7) / 8, 256>>>(ph1, gw, gb, pgex, pS);
    dim3 pg(3, (NN + 511) / 512);
    pool_k<<<pg, 256>>>(ph1, pgex, pS, out);
}

// round 4
// speedup vs baseline: 1.1334x; 1.1334x over previous
#include <cuda_runtime.h>
#include <math.h>
#include <stdint.h>

#define NN 50000
#define EE 500000
#define FF 128
#define HH 128
#define OUTD 768

// ---------------- scratch (device globals: no allocation allowed) ----------------
__device__ float g_Q  [(size_t)NN * HH];
__device__ float g_nK [(size_t)NN * HH];
__device__ float g_nV [(size_t)NN * HH];
__device__ float g_eK [(size_t)EE * HH];
__device__ float g_eV [(size_t)EE * HH];
__device__ float g_den[(size_t)NN * HH];
__device__ float g_acc[(size_t)NN * HH];
__device__ float g_hn [(size_t)NN * HH];
__device__ float g_h  [(size_t)NN * HH];
__device__ float g_lin[(size_t)NN * OUTD];
__device__ float g_h1 [(size_t)NN * OUTD];
__device__ float g_gex[NN];
__device__ float g_S[1];
__device__ float g_BtH[540672];   // transposed weights, tf32-high part
__device__ float g_BtL[540672];   // transposed weights, tf32-low residual

// ---------------- helpers ----------------
__device__ __forceinline__ uint32_t f2tf32(float x) {
    uint32_t u;
    asm("cvt.rna.tf32.f32 %0, %1;" : "=r"(u) : "f"(x));
    return u;
}
__device__ __forceinline__ void mma1688(float* c, const uint32_t* a,
                                        uint32_t b0, uint32_t b1) {
    asm volatile(
        "mma.sync.aligned.m16n8k8.row.col.f32.tf32.tf32.f32 "
        "{%0,%1,%2,%3}, {%4,%5,%6,%7}, {%8,%9}, {%0,%1,%2,%3};"
        : "+f"(c[0]), "+f"(c[1]), "+f"(c[2]), "+f"(c[3])
        : "r"(a[0]), "r"(a[1]), "r"(a[2]), "r"(a[3]), "r"(b0), "r"(b1));
}

// ---------------- tf32 mma GEMM ----------------
// C[M,Ntot] = concat_k(A0,A1,A2) @ Bt^T (+bias) (+gather add).
// BtH/BtL: [Ntot, ldb] K-major, tf32 hi/lo split (compensated B).
struct TG {
    const float* A0; const float* A1; const float* A2;
    int k0, k1, k2;
    int bc0, bc1, bc2;
    int ldb;
    const float* bias;
    const int* gidx; const float* gsrc;
    float* C; int M, Ntot;
    const float* BtH; const float* BtL;
};

#define PADK 20   // 16 + 4 pad: conflict-free frag loads, float4-aligned rows

__global__ __launch_bounds__(256, 2) void mma_gemm(TG p) {
    __shared__ uint32_t As [128 * PADK];
    __shared__ uint32_t BsH[128 * PADK];
    __shared__ uint32_t BsL[128 * PADK];

    const int tid = threadIdx.x;
    const int lid = tid & 31, wid = tid >> 5;
    const int warp_m = wid & 3, warp_n = wid >> 2;
    const int gID = lid >> 2, tig = lid & 3;
    const int m0 = blockIdx.y * 128, n0 = blockIdx.x * 128;

    float c[2][8][4];
#pragma unroll
    for (int mt = 0; mt < 2; mt++)
#pragma unroll
        for (int nt = 0; nt < 8; nt++)
#pragma unroll
            for (int i = 0; i < 4; i++) c[mt][nt][i] = 0.f;

    const int K = p.k0 + p.k1 + p.k2;
    const int nch = K >> 4;

    for (int kb = 0; kb < nch; kb++) {
        int off = kb << 4;
        const float* A; int lda; int bc;
        if (off < p.k0)             { A = p.A0; lda = p.k0; bc = p.bc0; }
        else if (off < p.k0 + p.k1) { A = p.A1; lda = p.k1; bc = p.bc1; off -= p.k0; }
        else                        { A = p.A2; lda = p.k2; bc = p.bc2; off -= p.k0 + p.k1; }

        __syncthreads();
        // ---- stage A (with explicit RN tf32 convert) ----
#pragma unroll
        for (int j = 0; j < 2; j++) {
            int id = tid + j * 256;          // 0..511
            int row = id >> 2, kq = id & 3;
            int gm = m0 + row;
            float4 v = make_float4(0.f, 0.f, 0.f, 0.f);
            if (gm < p.M) v = *(const float4*)(A + (size_t)gm * lda + off + kq * 4);
            uint4 u = make_uint4(f2tf32(v.x), f2tf32(v.y), f2tf32(v.z), f2tf32(v.w));
            *(uint4*)&As[row * PADK + kq * 4] = u;
        }
        // ---- stage B hi/lo (pre-converted) ----
#pragma unroll
        for (int j = 0; j < 2; j++) {
            int id = tid + j * 256;
            int row = id >> 2, kq = id & 3;
            size_t boff = (size_t)(n0 + row) * p.ldb + bc + off + kq * 4;
            uint4 h = *(const uint4*)(p.BtH + boff);
            uint4 l = *(const uint4*)(p.BtL + boff);
            *(uint4*)&BsH[row * PADK + kq * 4] = h;
            *(uint4*)&BsL[row * PADK + kq * 4] = l;
        }
        __syncthreads();

        // ---- compute: two k8 steps ----
#pragma unroll
        for (int k8 = 0; k8 < 16; k8 += 8) {
            uint32_t a[2][4];
#pragma unroll
            for (int mt = 0; mt < 2; mt++) {
                int rb = (warp_m * 32 + mt * 16 + gID) * PADK + k8 + tig;
                a[mt][0] = As[rb];
                a[mt][1] = As[rb + 8 * PADK];
                a[mt][2] = As[rb + 4];
                a[mt][3] = As[rb + 8 * PADK + 4];
            }
#pragma unroll
            for (int nt = 0; nt < 8; nt++) {
                int nb = (warp_n * 64 + nt * 8 + gID) * PADK + k8 + tig;
                uint32_t bh0 = BsH[nb], bh1 = BsH[nb + 4];
                uint32_t bl0 = BsL[nb], bl1 = BsL[nb + 4];
#pragma unroll
                for (int mt = 0; mt < 2; mt++) {
                    mma1688(c[mt][nt], a[mt], bh0, bh1);
                    mma1688(c[mt][nt], a[mt], bl0, bl1);
                }
            }
        }
    }

    // ---- epilogue ----
#pragma unroll
    for (int mt = 0; mt < 2; mt++) {
#pragma unroll
        for (int half = 0; half < 2; half++) {
            int gm = m0 + warp_m * 32 + mt * 16 + gID + half * 8;
            if (gm >= p.M) continue;
            const float* grow = nullptr;
            if (p.gsrc) {
                int gi = p.gidx[gm];
                grow = p.gsrc + (size_t)gi * p.Ntot;
            }
            float* crow = p.C + (size_t)gm * p.Ntot;
#pragma unroll
            for (int nt = 0; nt < 8; nt++) {
                int col = n0 + warp_n * 64 + nt * 8 + tig * 2;
                float v0 = c[mt][nt][half * 2 + 0];
                float v1 = c[mt][nt][half * 2 + 1];
                if (p.bias) { v0 += p.bias[col]; v1 += p.bias[col + 1]; }
                if (grow)   { v0 += grow[col];   v1 += grow[col + 1];   }
                *(float2*)(crow + col) = make_float2(v0, v1);
            }
        }
    }
}

// ---------------- weight transpose + tf32 hi/lo split ----------------
// BtH[n*K+k] = tf32(W[k*N+n]); BtL = tf32(W - hi)
__global__ void transpose_split_k(const float* __restrict__ W,
                                  float* __restrict__ BtH, float* __restrict__ BtL,
                                  int K, int N) {
    __shared__ float t[32][33];
    int bx = blockIdx.x * 32, by = blockIdx.y * 32;
#pragma unroll
    for (int i = 0; i < 4; i++) {
        int k = by + threadIdx.y + i * 8, n = bx + threadIdx.x;
        if (k < K && n < N) t[threadIdx.y + i * 8][threadIdx.x] = W[(size_t)k * N + n];
    }
    __syncthreads();
#pragma unroll
    for (int i = 0; i < 4; i++) {
        int n = bx + threadIdx.y + i * 8, k = by + threadIdx.x;
        if (k < K && n < N) {
            float w = t[threadIdx.x][threadIdx.y + i * 8];
            uint32_t hb = f2tf32(w);
            float hi = __uint_as_float(hb);
            uint32_t lb = f2tf32(w - hi);
            BtH[(size_t)n * K + k] = hi;
            BtL[(size_t)n * K + k] = __uint_as_float(lb);
        }
    }
}

// ---------------- edge attention scatter ----------------
__global__ __launch_bounds__(256) void edge_attn_k(
    const float* __restrict__ Q, const float* __restrict__ eK,
    const float* __restrict__ eV, const int* __restrict__ dst,
    float* __restrict__ den, float* __restrict__ acc)
{
    unsigned idx = blockIdx.x * 256u + threadIdx.x;
    if (idx >= (unsigned)EE * 32u) return;
    int e = idx >> 5;
    int c = (idx & 31) << 2;
    int d = dst[e];
    float4 q = *(const float4*)(Q  + (size_t)d * HH + c);
    float4 k = *(const float4*)(eK + (size_t)e * HH + c);
    float4 v = *(const float4*)(eV + (size_t)e * HH + c);
    float e0 = expf(q.x * k.x), e1 = expf(q.y * k.y);
    float e2 = expf(q.z * k.z), e3 = expf(q.w * k.w);
    float* dp = den + (size_t)d * HH + c;
    float* ap = acc + (size_t)d * HH + c;
    atomicAdd(dp + 0, e0); atomicAdd(dp + 1, e1);
    atomicAdd(dp + 2, e2); atomicAdd(dp + 3, e3);
    atomicAdd(ap + 0, e0 * v.x); atomicAdd(ap + 1, e1 * v.y);
    atomicAdd(ap + 2, e2 * v.z); atomicAdd(ap + 3, e3 * v.w);
}

__global__ __launch_bounds__(256) void node_div_k(
    const float* __restrict__ den, const float* __restrict__ acc,
    float* __restrict__ out)
{
    int i = blockIdx.x * 256 + threadIdx.x;
    if (i < NN * HH) {
        float d = den[i];
        out[i] = (d > 0.f) ? acc[i] / d : 0.f;
    }
}

// ---------------- layernorms ----------------
__global__ __launch_bounds__(128) void ln128_k(
    const float* __restrict__ x, const float* __restrict__ g,
    const float* __restrict__ b, float* __restrict__ y)
{
    int row = blockIdx.x, t = threadIdx.x;
    float v = x[(size_t)row * 128 + t];
    float s = v, s2 = v * v;
#pragma unroll
    for (int o = 16; o > 0; o >>= 1) {
        s  += __shfl_xor_sync(0xffffffffu, s, o);
        s2 += __shfl_xor_sync(0xffffffffu, s2, o);
    }
    __shared__ float ws[4], ws2[4];
    int w = t >> 5, l = t & 31;
    if (l == 0) { ws[w] = s; ws2[w] = s2; }
    __syncthreads();
    s  = ws[0] + ws[1] + ws[2] + ws[3];
    s2 = ws2[0] + ws2[1] + ws2[2] + ws2[3];
    float mu  = s * (1.f / 128.f);
    float var = s2 * (1.f / 128.f) - mu * mu;
    float r = rsqrtf(var + 1e-5f);
    y[(size_t)row * 128 + t] = (v - mu) * r * g[t] + b[t];
}

__global__ __launch_bounds__(256) void ln768_k(
    const float* __restrict__ x, const float* __restrict__ g,
    const float* __restrict__ b, float* __restrict__ y)
{
    int row = blockIdx.x, t = threadIdx.x;
    const float* xr = x + (size_t)row * 768;
    float v0 = xr[t], v1 = xr[t + 256], v2 = xr[t + 512];
    float s = v0 + v1 + v2;
    float s2 = v0 * v0 + v1 * v1 + v2 * v2;
#pragma unroll
    for (int o = 16; o > 0; o >>= 1) {
        s  += __shfl_xor_sync(0xffffffffu, s, o);
        s2 += __shfl_xor_sync(0xffffffffu, s2, o);
    }
    __shared__ float ws[8], ws2[8];
    int w = t >> 5, l = t & 31;
    if (l == 0) { ws[w] = s; ws2[w] = s2; }
    __syncthreads();
    s = 0.f; s2 = 0.f;
#pragma unroll
    for (int i = 0; i < 8; i++) { s += ws[i]; s2 += ws2[i]; }
    float mu  = s * (1.f / 768.f);
    float var = s2 * (1.f / 768.f) - mu * mu;
    float r = rsqrtf(var + 1e-5f);
    float* yr = y + (size_t)row * 768;
    yr[t]       = (v0 - mu) * r * g[t]       + b[t];
    yr[t + 256] = (v1 - mu) * r * g[t + 256] + b[t + 256];
    yr[t + 512] = (v2 - mu) * r * g[t + 512] + b[t + 512];
}

// ---------------- gate + pool ----------------
__global__ __launch_bounds__(256) void gate_k(
    const float* __restrict__ h1, const float* __restrict__ gw,
    const float* __restrict__ gb, float* __restrict__ gex,
    float* __restrict__ S)
{
    int w = threadIdx.x >> 5, l = threadIdx.x & 31;
    int node = blockIdx.x * 8 + w;
    float dot = 0.f;
    if (node < NN) {
        const float* hr = h1 + (size_t)node * 768;
#pragma unroll
        for (int k = 0; k < 24; k++)
            dot = fmaf(hr[l + 32 * k], gw[l + 32 * k], dot);
    }
#pragma unroll
    for (int o = 16; o > 0; o >>= 1) dot += __shfl_xor_sync(0xffffffffu, dot, o);
    __shared__ float ws[8];
    if (l == 0) {
        float ex = 0.f;
        if (node < NN) { ex = expf(dot + gb[0]); gex[node] = ex; }
        ws[w] = ex;
    }
    __syncthreads();
    if (threadIdx.x == 0) {
        float t = 0.f;
#pragma unroll
        for (int i = 0; i < 8; i++) t += ws[i];
        atomicAdd(S, t);
    }
}

__global__ __launch_bounds__(256) void pool_k(
    const float* __restrict__ h1, const float* __restrict__ gex,
    const float* __restrict__ S, float* __restrict__ out)
{
    int c = blockIdx.x * 256 + threadIdx.x;
    int nstart = blockIdx.y * 512;
    int nend = nstart + 512; if (nend > NN) nend = NN;
    float a = 0.f;
    for (int n = nstart; n < nend; n++)
        a = fmaf(gex[n], h1[(size_t)n * 768 + c], a);
    atomicAdd(&out[c], a * (1.f / S[0]));
}

// ---------------- host ----------------
static void launch_tg(const TG& p) {
    dim3 grid(p.Ntot / 128, (p.M + 127) / 128);
    mma_gemm<<<grid, 256>>>(p);
}

extern "C" void kernel_launch(void* const* d_in, const int* in_sizes, int n_in,
                              void* d_out, int out_size) {
    const float* kind   = (const float*)d_in[0];
    const float* edge_h = (const float*)d_in[1];
    const int*   src    = (const int*)  d_in[2];
    const int*   dst    = (const int*)  d_in[3];
    const float* KW  = (const float*)d_in[4];  const float* Kb  = (const float*)d_in[5];
    const float* VW  = (const float*)d_in[6];  const float* Vb  = (const float*)d_in[7];
    const float* QW  = (const float*)d_in[8];  const float* Qb  = (const float*)d_in[9];
    const float* WW  = (const float*)d_in[10]; const float* Wb  = (const float*)d_in[11];
    const float* K2W = (const float*)d_in[12]; const float* K2b = (const float*)d_in[13];
    const float* V2W = (const float*)d_in[14]; const float* V2b = (const float*)d_in[15];
    const float* Q2W = (const float*)d_in[16]; const float* Q2b = (const float*)d_in[17];
    const float* W2W = (const float*)d_in[18]; const float* W2b = (const float*)d_in[19];
    const float* ln1g = (const float*)d_in[20]; const float* ln1b = (const float*)d_in[21];
    const float* ln2g = (const float*)d_in[22]; const float* ln2b = (const float*)d_in[23];
    const float* gw  = (const float*)d_in[24]; const float* gb  = (const float*)d_in[25];
    float* out = (float*)d_out;

    static float *pQ = nullptr, *pnK, *pnV, *peK, *peV, *pden, *pacc,
                 *phn, *ph, *plin, *ph1, *pgex, *pS, *pBtH, *pBtL;
    if (!pQ) {
        cudaGetSymbolAddress((void**)&pQ,   g_Q);
        cudaGetSymbolAddress((void**)&pnK,  g_nK);
        cudaGetSymbolAddress((void**)&pnV,  g_nV);
        cudaGetSymbolAddress((void**)&peK,  g_eK);
        cudaGetSymbolAddress((void**)&peV,  g_eV);
        cudaGetSymbolAddress((void**)&pden, g_den);
        cudaGetSymbolAddress((void**)&pacc, g_acc);
        cudaGetSymbolAddress((void**)&phn,  g_hn);
        cudaGetSymbolAddress((void**)&ph,   g_h);
        cudaGetSymbolAddress((void**)&plin, g_lin);
        cudaGetSymbolAddress((void**)&ph1,  g_h1);
        cudaGetSymbolAddress((void**)&pgex, g_gex);
        cudaGetSymbolAddress((void**)&pS,   g_S);
        cudaGetSymbolAddress((void**)&pBtH, g_BtH);
        cudaGetSymbolAddress((void**)&pBtL, g_BtL);
    }

    // transposed weight offsets (floats)
    const int oQ  = 0;        // 128x128
    const int oK  = 16384;    // 128x256
    const int oV  = 49152;    // 128x256
    const int oW  = 81920;    // 128x256
    const int oQ2 = 114688;   // 128x256
    const int oK2 = 147456;   // 128x384
    const int oV2 = 196608;   // 128x384
    const int oW2 = 245760;   // 768x384

    dim3 tb(32, 8);
    transpose_split_k<<<dim3(4, 4),   tb>>>(QW,  pBtH + oQ,  pBtL + oQ,  128, 128);
    transpose_split_k<<<dim3(4, 8),   tb>>>(KW,  pBtH + oK,  pBtL + oK,  256, 128);
    transpose_split_k<<<dim3(4, 8),   tb>>>(VW,  pBtH + oV,  pBtL + oV,  256, 128);
    transpose_split_k<<<dim3(4, 8),   tb>>>(WW,  pBtH + oW,  pBtL + oW,  256, 128);
    transpose_split_k<<<dim3(4, 8),   tb>>>(Q2W, pBtH + oQ2, pBtL + oQ2, 256, 128);
    transpose_split_k<<<dim3(4, 12),  tb>>>(K2W, pBtH + oK2, pBtL + oK2, 384, 128);
    transpose_split_k<<<dim3(4, 12),  tb>>>(V2W, pBtH + oV2, pBtL + oV2, 384, 128);
    transpose_split_k<<<dim3(24, 12), tb>>>(W2W, pBtH + oW2, pBtL + oW2, 384, 768);

    const size_t nh_bytes = (size_t)NN * HH * sizeof(float);
    TG p;

    // ===================== layer 1 =====================
    cudaMemsetAsync(pden, 0, nh_bytes);
    cudaMemsetAsync(pacc, 0, nh_bytes);

    // Q = kind @ QW + Qb
    p = {kind, nullptr, nullptr, FF, 0, 0, 0, 0, 0, 128,
         Qb, nullptr, nullptr, pQ, NN, HH, pBtH + oQ, pBtL + oQ};
    launch_tg(p);
    // nodeK = kind @ KW[0:F] + Kb ; nodeV likewise
    p = {kind, nullptr, nullptr, FF, 0, 0, 0, 0, 0, 256,
         Kb, nullptr, nullptr, pnK, NN, HH, pBtH + oK, pBtL + oK};
    launch_tg(p);
    p = {kind, nullptr, nullptr, FF, 0, 0, 0, 0, 0, 256,
         Vb, nullptr, nullptr, pnV, NN, HH, pBtH + oV, pBtL + oV};
    launch_tg(p);
    // eK = edge_h @ KW[F:2F] + nodeK[src] ; eV likewise
    p = {edge_h, nullptr, nullptr, FF, 0, 0, FF, 0, 0, 256,
         nullptr, src, pnK, peK, EE, HH, pBtH + oK, pBtL + oK};
    launch_tg(p);
    p = {edge_h, nullptr, nullptr, FF, 0, 0, FF, 0, 0, 256,
         nullptr, src, pnV, peV, EE, HH, pBtH + oV, pBtL + oV};
    launch_tg(p);

    edge_attn_k<<<(EE * 32 + 255) / 256, 256>>>(pQ, peK, peV, dst, pden, pacc);
    node_div_k<<<(NN * HH + 255) / 256, 256>>>(pden, pacc, phn);

    // lin1 = concat(h_n, kind) @ WW + Wb ; h = LN(lin1)
    p = {phn, kind, nullptr, HH, FF, 0, 0, HH, 0, 256,
         Wb, nullptr, nullptr, plin, NN, HH, pBtH + oW, pBtL + oW};
    launch_tg(p);
    ln128_k<<<NN, 128>>>(plin, ln1g, ln1b, ph);

    // ===================== layer 2 =====================
    cudaMemsetAsync(pden, 0, nh_bytes);
    cudaMemsetAsync(pacc, 0, nh_bytes);

    // Q2 = concat(kind, h) @ Q2W + Q2b
    p = {kind, ph, nullptr, FF, HH, 0, 0, FF, 0, 256,
         Q2b, nullptr, nullptr, pQ, NN, HH, pBtH + oQ2, pBtL + oQ2};
    launch_tg(p);
    // nodeK2 = kind@K2W[0:F] + h@K2W[2F:3F] + K2b ; nodeV2 likewise
    p = {kind, ph, nullptr, FF, HH, 0, 0, 2 * FF, 0, 384,
         K2b, nullptr, nullptr, pnK, NN, HH, pBtH + oK2, pBtL + oK2};
    launch_tg(p);
    p = {kind, ph, nullptr, FF, HH, 0, 0, 2 * FF, 0, 384,
         V2b, nullptr, nullptr, pnV, NN, HH, pBtH + oV2, pBtL + oV2};
    launch_tg(p);
    // eK2 = edge_h @ K2W[F:2F] + nodeK2[src] ; eV2 likewise
    p = {edge_h, nullptr, nullptr, FF, 0, 0, FF, 0, 0, 384,
         nullptr, src, pnK, peK, EE, HH, pBtH + oK2, pBtL + oK2};
    launch_tg(p);
    p = {edge_h, nullptr, nullptr, FF, 0, 0, FF, 0, 0, 384,
         nullptr, src, pnV, peV, EE, HH, pBtH + oV2, pBtL + oV2};
    launch_tg(p);

    edge_attn_k<<<(EE * 32 + 255) / 256, 256>>>(pQ, peK, peV, dst, pden, pacc);
    node_div_k<<<(NN * HH + 255) / 256, 256>>>(pden, pacc, phn);

    // lin2 = concat(h_n1, h, kind) @ W2W + W2b ; h1 = LN(lin2)
    p = {phn, ph, kind, HH, HH, FF, 0, HH, 2 * HH, 384,
         W2b, nullptr, nullptr, plin, NN, OUTD, pBtH + oW2, pBtL + oW2};
    launch_tg(p);
    ln768_k<<<NN, 256>>>(plin, ln2g, ln2b, ph1);

    // ===================== pooling =====================
    cudaMemsetAsync(pS, 0, sizeof(float));
    cudaMemsetAsync(out, 0, (size_t)OUTD * sizeof(float));
    gate_k<<<(NN + 7) / 8, 256>>>(ph1, gw, gb, pgex, pS);
    dim3 pg(3, (NN + 511) / 512);
    pool_k<<<pg, 256>>>(ph1, pgex, pS, out);
}

// round 5
// speedup vs baseline: 1.5773x; 1.3917x over previous
#include <cuda_runtime.h>
#include <math.h>
#include <stdint.h>

#define NN 50000
#define EE 500000
#define FF 128
#define HH 128
#define OUTD 768

// ---------------- scratch (device globals: no allocation allowed) ----------------
__device__ float g_Q  [(size_t)NN * HH];
__device__ float g_nK [(size_t)NN * HH];
__device__ float g_nV [(size_t)NN * HH];
__device__ float g_ex [(size_t)EE * HH];    // per-edge exp(Q[dst]*eK)
__device__ float g_den[(size_t)NN * HH];
__device__ float g_acc[(size_t)NN * HH];
__device__ float g_hn [(size_t)NN * HH];
__device__ float g_h  [(size_t)NN * HH];
__device__ float g_lin[(size_t)NN * OUTD];
__device__ float g_h1 [(size_t)NN * OUTD];
__device__ float g_gex[NN];
__device__ float g_S[1];
__device__ float g_Bt[540672];   // transposed weights (fp32; tf32-cvt at staging)

// ---------------- helpers ----------------
__device__ __forceinline__ uint32_t f2tf32(float x) {
    uint32_t u;
    asm("cvt.rna.tf32.f32 %0, %1;" : "=r"(u) : "f"(x));
    return u;
}
__device__ __forceinline__ void mma1688(float* c, const uint32_t* a,
                                        uint32_t b0, uint32_t b1) {
    asm volatile(
        "mma.sync.aligned.m16n8k8.row.col.f32.tf32.tf32.f32 "
        "{%0,%1,%2,%3}, {%4,%5,%6,%7}, {%8,%9}, {%0,%1,%2,%3};"
        : "+f"(c[0]), "+f"(c[1]), "+f"(c[2]), "+f"(c[3])
        : "r"(a[0]), "r"(a[1]), "r"(a[2]), "r"(a[3]), "r"(b0), "r"(b1));
}

// ---------------- tf32 mma GEMM with fused epilogues ----------------
// C[M,Ntot] = concat_k(A0,A1,A2) @ Bt^T. Bt [Ntot, ldb] K-major fp32.
// mode 0: C = gemm + bias + optional gather-add
// mode 1: v = gemm + gather(nodeK)[src]; ex=exp(Q[dst]*v); C=ex; den[dst]+=ex
// mode 2: v = gemm + gather(nodeV)[src]; acc[dst] += ex[row]*v  (no C write)
struct TG {
    const float* A0; const float* A1; const float* A2;
    int k0, k1, k2;
    int bc0, bc1, bc2;
    int ldb;
    const float* Bt;
    const float* bias;
    const int* gidx; const float* gsrc;
    float* C; int M, Ntot;
    int mode;
    const int* dst; const float* Qm; float* den; float* acc; const float* ex;
};

#define PADK 20   // 16 + 4 pad: conflict-free frag loads, float4-aligned rows

__global__ __launch_bounds__(256, 2) void mma_gemm(TG p) {
    __shared__ uint32_t As[128 * PADK];
    __shared__ uint32_t Bs[128 * PADK];

    const int tid = threadIdx.x;
    const int lid = tid & 31, wid = tid >> 5;
    const int warp_m = wid & 3, warp_n = wid >> 2;
    const int gID = lid >> 2, tig = lid & 3;
    const int m0 = blockIdx.y * 128, n0 = blockIdx.x * 128;

    float c[2][8][4];
#pragma unroll
    for (int mt = 0; mt < 2; mt++)
#pragma unroll
        for (int nt = 0; nt < 8; nt++)
#pragma unroll
            for (int i = 0; i < 4; i++) c[mt][nt][i] = 0.f;

    const int K = p.k0 + p.k1 + p.k2;
    const int nch = K >> 4;

    for (int kb = 0; kb < nch; kb++) {
        int off = kb << 4;
        const float* A; int lda; int bc;
        if (off < p.k0)             { A = p.A0; lda = p.k0; bc = p.bc0; }
        else if (off < p.k0 + p.k1) { A = p.A1; lda = p.k1; bc = p.bc1; off -= p.k0; }
        else                        { A = p.A2; lda = p.k2; bc = p.bc2; off -= p.k0 + p.k1; }

        __syncthreads();
        // ---- stage A (explicit RN tf32 convert) ----
#pragma unroll
        for (int j = 0; j < 2; j++) {
            int id = tid + j * 256;          // 0..511
            int row = id >> 2, kq = id & 3;
            int gm = m0 + row;
            float4 v = make_float4(0.f, 0.f, 0.f, 0.f);
            if (gm < p.M) v = *(const float4*)(A + (size_t)gm * lda + off + kq * 4);
            uint4 u = make_uint4(f2tf32(v.x), f2tf32(v.y), f2tf32(v.z), f2tf32(v.w));
            *(uint4*)&As[row * PADK + kq * 4] = u;
        }
        // ---- stage B (explicit RN tf32 convert) ----
#pragma unroll
        for (int j = 0; j < 2; j++) {
            int id = tid + j * 256;
            int row = id >> 2, kq = id & 3;
            float4 v = *(const float4*)(p.Bt + (size_t)(n0 + row) * p.ldb + bc + off + kq * 4);
            uint4 u = make_uint4(f2tf32(v.x), f2tf32(v.y), f2tf32(v.z), f2tf32(v.w));
            *(uint4*)&Bs[row * PADK + kq * 4] = u;
        }
        __syncthreads();

        // ---- compute: two k8 steps ----
#pragma unroll
        for (int k8 = 0; k8 < 16; k8 += 8) {
            uint32_t a[2][4];
#pragma unroll
            for (int mt = 0; mt < 2; mt++) {
                int rb = (warp_m * 32 + mt * 16 + gID) * PADK + k8 + tig;
                a[mt][0] = As[rb];
                a[mt][1] = As[rb + 8 * PADK];
                a[mt][2] = As[rb + 4];
                a[mt][3] = As[rb + 8 * PADK + 4];
            }
#pragma unroll
            for (int nt = 0; nt < 8; nt++) {
                int nb = (warp_n * 64 + nt * 8 + gID) * PADK + k8 + tig;
                uint32_t b0 = Bs[nb], b1 = Bs[nb + 4];
#pragma unroll
                for (int mt = 0; mt < 2; mt++)
                    mma1688(c[mt][nt], a[mt], b0, b1);
            }
        }
    }

    // ---- epilogue ----
#pragma unroll
    for (int mt = 0; mt < 2; mt++) {
#pragma unroll
        for (int half = 0; half < 2; half++) {
            int gm = m0 + warp_m * 32 + mt * 16 + gID + half * 8;
            if (gm >= p.M) continue;
            const float* grow = nullptr;
            if (p.gsrc) {
                int gi = p.gidx[gm];
                grow = p.gsrc + (size_t)gi * p.Ntot;
            }
            if (p.mode == 0) {
                float* crow = p.C + (size_t)gm * p.Ntot;
#pragma unroll
                for (int nt = 0; nt < 8; nt++) {
                    int col = n0 + warp_n * 64 + nt * 8 + tig * 2;
                    float v0 = c[mt][nt][half * 2 + 0];
                    float v1 = c[mt][nt][half * 2 + 1];
                    if (p.bias) { v0 += p.bias[col]; v1 += p.bias[col + 1]; }
                    if (grow)   { v0 += grow[col];   v1 += grow[col + 1];   }
                    *(float2*)(crow + col) = make_float2(v0, v1);
                }
            } else if (p.mode == 1) {
                int d = p.dst[gm];
                const float* qrow = p.Qm + (size_t)d * HH;
                float* crow = p.C + (size_t)gm * HH;
                float* drow = p.den + (size_t)d * HH;
#pragma unroll
                for (int nt = 0; nt < 8; nt++) {
                    int col = warp_n * 64 + nt * 8 + tig * 2;
                    float v0 = c[mt][nt][half * 2 + 0] + grow[col];
                    float v1 = c[mt][nt][half * 2 + 1] + grow[col + 1];
                    float2 q = *(const float2*)(qrow + col);
                    float e0 = expf(q.x * v0), e1 = expf(q.y * v1);
                    *(float2*)(crow + col) = make_float2(e0, e1);
                    atomicAdd(drow + col, e0);
                    atomicAdd(drow + col + 1, e1);
                }
            } else {
                int d = p.dst[gm];
                const float* exrow = p.ex + (size_t)gm * HH;
                float* arow = p.acc + (size_t)d * HH;
#pragma unroll
                for (int nt = 0; nt < 8; nt++) {
                    int col = warp_n * 64 + nt * 8 + tig * 2;
                    float v0 = c[mt][nt][half * 2 + 0] + grow[col];
                    float v1 = c[mt][nt][half * 2 + 1] + grow[col + 1];
                    float2 e = *(const float2*)(exrow + col);
                    atomicAdd(arow + col, e.x * v0);
                    atomicAdd(arow + col + 1, e.y * v1);
                }
            }
        }
    }
}

// ---------------- fused weight transposes (one launch) ----------------
struct TransDesc { const float* W; float* O; int K; int N; };
struct TransParams { TransDesc t[8]; int start[9]; };

__global__ void transpose_all_k(TransParams tp) {
    __shared__ float t[32][33];
    int b = blockIdx.x;
    int i = 0;
#pragma unroll
    for (int j = 0; j < 8; j++)
        if (b >= tp.start[j + 1]) i = j + 1;
    const TransDesc d = tp.t[i];
    int rem = b - tp.start[i];
    int nbx = d.N >> 5;
    int bx = (rem % nbx) * 32, by = (rem / nbx) * 32;
#pragma unroll
    for (int r = 0; r < 4; r++) {
        int k = by + threadIdx.y + r * 8, n = bx + threadIdx.x;
        t[threadIdx.y + r * 8][threadIdx.x] = d.W[(size_t)k * d.N + n];
    }
    __syncthreads();
#pragma unroll
    for (int r = 0; r < 4; r++) {
        int n = bx + threadIdx.y + r * 8, k = by + threadIdx.x;
        d.O[(size_t)n * d.K + k] = t[threadIdx.x][threadIdx.y + r * 8];
    }
}

// ---------------- node div ----------------
__global__ __launch_bounds__(256) void node_div_k(
    const float* __restrict__ den, const float* __restrict__ acc,
    float* __restrict__ out)
{
    int i = blockIdx.x * 256 + threadIdx.x;
    if (i < NN * HH) {
        float d = den[i];
        out[i] = (d > 0.f) ? acc[i] / d : 0.f;
    }
}

// ---------------- layernorms ----------------
__global__ __launch_bounds__(128) void ln128_k(
    const float* __restrict__ x, const float* __restrict__ g,
    const float* __restrict__ b, float* __restrict__ y)
{
    int row = blockIdx.x, t = threadIdx.x;
    float v = x[(size_t)row * 128 + t];
    float s = v, s2 = v * v;
#pragma unroll
    for (int o = 16; o > 0; o >>= 1) {
        s  += __shfl_xor_sync(0xffffffffu, s, o);
        s2 += __shfl_xor_sync(0xffffffffu, s2, o);
    }
    __shared__ float ws[4], ws2[4];
    int w = t >> 5, l = t & 31;
    if (l == 0) { ws[w] = s; ws2[w] = s2; }
    __syncthreads();
    s  = ws[0] + ws[1] + ws[2] + ws[3];
    s2 = ws2[0] + ws2[1] + ws2[2] + ws2[3];
    float mu  = s * (1.f / 128.f);
    float var = s2 * (1.f / 128.f) - mu * mu;
    float r = rsqrtf(var + 1e-5f);
    y[(size_t)row * 128 + t] = (v - mu) * r * g[t] + b[t];
}

__global__ __launch_bounds__(256) void ln768_k(
    const float* __restrict__ x, const float* __restrict__ g,
    const float* __restrict__ b, float* __restrict__ y)
{
    int row = blockIdx.x, t = threadIdx.x;
    const float* xr = x + (size_t)row * 768;
    float v0 = xr[t], v1 = xr[t + 256], v2 = xr[t + 512];
    float s = v0 + v1 + v2;
    float s2 = v0 * v0 + v1 * v1 + v2 * v2;
#pragma unroll
    for (int o = 16; o > 0; o >>= 1) {
        s  += __shfl_xor_sync(0xffffffffu, s, o);
        s2 += __shfl_xor_sync(0xffffffffu, s2, o);
    }
    __shared__ float ws[8], ws2[8];
    int w = t >> 5, l = t & 31;
    if (l == 0) { ws[w] = s; ws2[w] = s2; }
    __syncthreads();
    s = 0.f; s2 = 0.f;
#pragma unroll
    for (int i = 0; i < 8; i++) { s += ws[i]; s2 += ws2[i]; }
    float mu  = s * (1.f / 768.f);
    float var = s2 * (1.f / 768.f) - mu * mu;
    float r = rsqrtf(var + 1e-5f);
    float* yr = y + (size_t)row * 768;
    yr[t]       = (v0 - mu) * r * g[t]       + b[t];
    yr[t + 256] = (v1 - mu) * r * g[t + 256] + b[t + 256];
    yr[t + 512] = (v2 - mu) * r * g[t + 512] + b[t + 512];
}

// ---------------- gate + pool ----------------
__global__ __launch_bounds__(256) void gate_k(
    const float* __restrict__ h1, const float* __restrict__ gw,
    const float* __restrict__ gb, float* __restrict__ gex,
    float* __restrict__ S)
{
    int w = threadIdx.x >> 5, l = threadIdx.x & 31;
    int node = blockIdx.x * 8 + w;
    float dot = 0.f;
    if (node < NN) {
        const float* hr = h1 + (size_t)node * 768;
#pragma unroll
        for (int k = 0; k < 24; k++)
            dot = fmaf(hr[l + 32 * k], gw[l + 32 * k], dot);
    }
#pragma unroll
    for (int o = 16; o > 0; o >>= 1) dot += __shfl_xor_sync(0xffffffffu, dot, o);
    __shared__ float ws[8];
    if (l == 0) {
        float ex = 0.f;
        if (node < NN) { ex = expf(dot + gb[0]); gex[node] = ex; }
        ws[w] = ex;
    }
    __syncthreads();
    if (threadIdx.x == 0) {
        float t = 0.f;
#pragma unroll
        for (int i = 0; i < 8; i++) t += ws[i];
        atomicAdd(S, t);
    }
}

__global__ __launch_bounds__(256) void pool_k(
    const float* __restrict__ h1, const float* __restrict__ gex,
    const float* __restrict__ S, float* __restrict__ out)
{
    int c = blockIdx.x * 256 + threadIdx.x;
    int nstart = blockIdx.y * 512;
    int nend = nstart + 512; if (nend > NN) nend = NN;
    float a = 0.f;
    for (int n = nstart; n < nend; n++)
        a = fmaf(gex[n], h1[(size_t)n * 768 + c], a);
    atomicAdd(&out[c], a * (1.f / S[0]));
}

// ---------------- host ----------------
static void launch_tg(const TG& p) {
    dim3 grid(p.Ntot / 128, (p.M + 127) / 128);
    mma_gemm<<<grid, 256>>>(p);
}

extern "C" void kernel_launch(void* const* d_in, const int* in_sizes, int n_in,
                              void* d_out, int out_size) {
    const float* kind   = (const float*)d_in[0];
    const float* edge_h = (const float*)d_in[1];
    const int*   src    = (const int*)  d_in[2];
    const int*   dst    = (const int*)  d_in[3];
    const float* KW  = (const float*)d_in[4];  const float* Kb  = (const float*)d_in[5];
    const float* VW  = (const float*)d_in[6];  const float* Vb  = (const float*)d_in[7];
    const float* QW  = (const float*)d_in[8];  const float* Qb  = (const float*)d_in[9];
    const float* WW  = (const float*)d_in[10]; const float* Wb  = (const float*)d_in[11];
    const float* K2W = (const float*)d_in[12]; const float* K2b = (const float*)d_in[13];
    const float* V2W = (const float*)d_in[14]; const float* V2b = (const float*)d_in[15];
    const float* Q2W = (const float*)d_in[16]; const float* Q2b = (const float*)d_in[17];
    const float* W2W = (const float*)d_in[18]; const float* W2b = (const float*)d_in[19];
    const float* ln1g = (const float*)d_in[20]; const float* ln1b = (const float*)d_in[21];
    const float* ln2g = (const float*)d_in[22]; const float* ln2b = (const float*)d_in[23];
    const float* gw  = (const float*)d_in[24]; const float* gb  = (const float*)d_in[25];
    float* out = (float*)d_out;

    static float *pQ = nullptr, *pnK, *pnV, *pex, *pden, *pacc,
                 *phn, *ph, *plin, *ph1, *pgex, *pS, *pBt;
    if (!pQ) {
        cudaGetSymbolAddress((void**)&pQ,   g_Q);
        cudaGetSymbolAddress((void**)&pnK,  g_nK);
        cudaGetSymbolAddress((void**)&pnV,  g_nV);
        cudaGetSymbolAddress((void**)&pex,  g_ex);
        cudaGetSymbolAddress((void**)&pden, g_den);
        cudaGetSymbolAddress((void**)&pacc, g_acc);
        cudaGetSymbolAddress((void**)&phn,  g_hn);
        cudaGetSymbolAddress((void**)&ph,   g_h);
        cudaGetSymbolAddress((void**)&plin, g_lin);
        cudaGetSymbolAddress((void**)&ph1,  g_h1);
        cudaGetSymbolAddress((void**)&pgex, g_gex);
        cudaGetSymbolAddress((void**)&pS,   g_S);
        cudaGetSymbolAddress((void**)&pBt,  g_Bt);
    }

    // transposed weight offsets (floats)
    const int oQ  = 0;        // 128x128
    const int oK  = 16384;    // 128x256
    const int oV  = 49152;    // 128x256
    const int oW  = 81920;    // 128x256
    const int oQ2 = 114688;   // 128x256
    const int oK2 = 147456;   // 128x384
    const int oV2 = 196608;   // 128x384
    const int oW2 = 245760;   // 768x384

    // single fused transpose launch (528 tiles)
    TransParams tp;
    tp.t[0] = {QW,  pBt + oQ,  128, 128};
    tp.t[1] = {KW,  pBt + oK,  256, 128};
    tp.t[2] = {VW,  pBt + oV,  256, 128};
    tp.t[3] = {WW,  pBt + oW,  256, 128};
    tp.t[4] = {Q2W, pBt + oQ2, 256, 128};
    tp.t[5] = {K2W, pBt + oK2, 384, 128};
    tp.t[6] = {V2W, pBt + oV2, 384, 128};
    tp.t[7] = {W2W, pBt + oW2, 384, 768};
    int s = 0;
    for (int i = 0; i < 8; i++) {
        tp.start[i] = s;
        s += (tp.t[i].N >> 5) * (tp.t[i].K >> 5);
    }
    tp.start[8] = s;
    transpose_all_k<<<s, dim3(32, 8)>>>(tp);

    const size_t nh_bytes = (size_t)NN * HH * sizeof(float);
    TG p;
    memset(&p, 0, sizeof(p));

    // ===================== layer 1 =====================
    cudaMemsetAsync(pden, 0, nh_bytes);
    cudaMemsetAsync(pacc, 0, nh_bytes);

    // Q = kind @ QW + Qb
    p = {kind, nullptr, nullptr, FF, 0, 0, 0, 0, 0, 128, pBt + oQ,
         Qb, nullptr, nullptr, pQ, NN, HH, 0,
         nullptr, nullptr, nullptr, nullptr, nullptr};
    launch_tg(p);
    // nodeK = kind @ KW[0:F] + Kb ; nodeV likewise
    p = {kind, nullptr, nullptr, FF, 0, 0, 0, 0, 0, 256, pBt + oK,
         Kb, nullptr, nullptr, pnK, NN, HH, 0,
         nullptr, nullptr, nullptr, nullptr, nullptr};
    launch_tg(p);
    p = {kind, nullptr, nullptr, FF, 0, 0, 0, 0, 0, 256, pBt + oV,
         Vb, nullptr, nullptr, pnV, NN, HH, 0,
         nullptr, nullptr, nullptr, nullptr, nullptr};
    launch_tg(p);
    // eK fused: ex = exp(Q[dst] * (edge_h@KW[F:] + nodeK[src])); den[dst]+=ex
    p = {edge_h, nullptr, nullptr, FF, 0, 0, FF, 0, 0, 256, pBt + oK,
         nullptr, src, pnK, pex, EE, HH, 1,
         dst, pQ, pden, nullptr, nullptr};
    launch_tg(p);
    // eV fused: acc[dst] += ex * (edge_h@VW[F:] + nodeV[src])
    p = {edge_h, nullptr, nullptr, FF, 0, 0, FF, 0, 0, 256, pBt + oV,
         nullptr, src, pnV, nullptr, EE, HH, 2,
         dst, nullptr, nullptr, pacc, pex};
    launch_tg(p);

    node_div_k<<<(NN * HH + 255) / 256, 256>>>(pden, pacc, phn);

    // lin1 = concat(h_n, kind) @ WW + Wb ; h = LN(lin1)
    p = {phn, kind, nullptr, HH, FF, 0, 0, HH, 0, 256, pBt + oW,
         Wb, nullptr, nullptr, plin, NN, HH, 0,
         nullptr, nullptr, nullptr, nullptr, nullptr};
    launch_tg(p);
    ln128_k<<<NN, 128>>>(plin, ln1g, ln1b, ph);

    // ===================== layer 2 =====================
    cudaMemsetAsync(pden, 0, nh_bytes);
    cudaMemsetAsync(pacc, 0, nh_bytes);

    // Q2 = concat(kind, h) @ Q2W + Q2b
    p = {kind, ph, nullptr, FF, HH, 0, 0, FF, 0, 256, pBt + oQ2,
         Q2b, nullptr, nullptr, pQ, NN, HH, 0,
         nullptr, nullptr, nullptr, nullptr, nullptr};
    launch_tg(p);
    // nodeK2 = kind@K2W[0:F] + h@K2W[2F:3F] + K2b ; nodeV2 likewise
    p = {kind, ph, nullptr, FF, HH, 0, 0, 2 * FF, 0, 384, pBt + oK2,
         K2b, nullptr, nullptr, pnK, NN, HH, 0,
         nullptr, nullptr, nullptr, nullptr, nullptr};
    launch_tg(p);
    p = {kind, ph, nullptr, FF, HH, 0, 0, 2 * FF, 0, 384, pBt + oV2,
         V2b, nullptr, nullptr, pnV, NN, HH, 0,
         nullptr, nullptr, nullptr, nullptr, nullptr};
    launch_tg(p);
    // eK2 fused
    p = {edge_h, nullptr, nullptr, FF, 0, 0, FF, 0, 0, 384, pBt + oK2,
         nullptr, src, pnK, pex, EE, HH, 1,
         dst, pQ, pden, nullptr, nullptr};
    launch_tg(p);
    // eV2 fused
    p = {edge_h, nullptr, nullptr, FF, 0, 0, FF, 0, 0, 384, pBt + oV2,
         nullptr, src, pnV, nullptr, EE, HH, 2,
         dst, nullptr, nullptr, pacc, pex};
    launch_tg(p);

    node_div_k<<<(NN * HH + 255) / 256, 256>>>(pden, pacc, phn);

    // lin2 = concat(h_n1, h, kind) @ W2W + W2b ; h1 = LN(lin2)
    p = {phn, ph, kind, HH, HH, FF, 0, HH, 2 * HH, 384, pBt + oW2,
         W2b, nullptr, nullptr, plin, NN, OUTD, 0,
         nullptr, nullptr, nullptr, nullptr, nullptr};
    launch_tg(p);
    ln768_k<<<NN, 256>>>(plin, ln2g, ln2b, ph1);

    // ===================== pooling =====================
    cudaMemsetAsync(pS, 0, sizeof(float));
    cudaMemsetAsync(out, 0, (size_t)OUTD * sizeof(float));
    gate_k<<<(NN + 7) / 8, 256>>>(ph1, gw, gb, pgex, pS);
    dim3 pg(3, (NN + 511) / 512);
    pool_k<<<pg, 256>>>(ph1, pgex, pS, out);
}

// round 6
// speedup vs baseline: 1.8314x; 1.1611x over previous
#include <cuda_runtime.h>
#include <math.h>
#include <stdint.h>

#define NN 50000
#define EE 500000
#define FF 128
#define HH 128
#define OUTD 768

// ---------------- scratch (device globals: no allocation allowed) ----------------
__device__ float g_Q  [(size_t)NN * HH];
__device__ float g_nK [(size_t)NN * HH];
__device__ float g_nV [(size_t)NN * HH];
__device__ float g_ex [(size_t)EE * HH];    // per-edge exp(Q[dst]*eK)
__device__ float g_den[(size_t)NN * HH];
__device__ float g_acc[(size_t)NN * HH];
__device__ float g_hn [(size_t)NN * HH];
__device__ float g_h  [(size_t)NN * HH];
__device__ float g_lin[(size_t)NN * OUTD];
__device__ float g_h1 [(size_t)NN * OUTD];
__device__ float g_gex[NN];
__device__ float g_S[1];
__device__ float g_Bt[540672];   // packed transposed weights (pre-rounded tf32)

// ---------------- helpers ----------------
__device__ __forceinline__ uint32_t smem_u32(const void* p) {
    uint32_t a;
    asm("{ .reg .u64 t; cvta.to.shared.u64 t, %1; cvt.u32.u64 %0, t; }" : "=r"(a) : "l"(p));
    return a;
}
__device__ __forceinline__ uint32_t f2tf32(float x) {
    uint32_t u;
    asm("cvt.rna.tf32.f32 %0, %1;" : "=r"(u) : "f"(x));
    return u;
}
__device__ __forceinline__ void mma1688(float* c, const uint32_t* a,
                                        uint32_t b0, uint32_t b1) {
    asm volatile(
        "mma.sync.aligned.m16n8k8.row.col.f32.tf32.tf32.f32 "
        "{%0,%1,%2,%3}, {%4,%5,%6,%7}, {%8,%9}, {%0,%1,%2,%3};"
        : "+f"(c[0]), "+f"(c[1]), "+f"(c[2]), "+f"(c[3])
        : "r"(a[0]), "r"(a[1]), "r"(a[2]), "r"(a[3]), "r"(b0), "r"(b1));
}
__device__ __forceinline__ void cp16(uint32_t dst, const void* src, int szn) {
    asm volatile("cp.async.ca.shared.global [%0], [%1], 16, %2;"
                 :: "r"(dst), "l"(src), "r"(szn) : "memory");
}
__device__ __forceinline__ void cpa_commit() {
    asm volatile("cp.async.commit_group;" ::: "memory");
}
template <int N> __device__ __forceinline__ void cpa_wait() {
    asm volatile("cp.async.wait_group %0;" :: "n"(N) : "memory");
}

// ---------------- tf32 mma GEMM, cp.async 3-stage pipeline ----------------
// C = concat_k(A0,A1,A2) @ Bt^T. Bt [Ntot, ldb] K-major, PRE-ROUNDED tf32.
// mode 0: C = gemm + bias (+gather add). If C1 set: blockIdx.x picks C/C1/C2
//         (bias/bias1/bias2), each [M,128].
// mode 1: v = gemm + gather(nodeK)[src]; ex=exp(Q[dst]*v); C=ex; den[dst]+=ex
// mode 2: v = gemm + gather(nodeV)[src]; acc[dst] += ex[row]*v (no C write)
struct TG {
    const float* A0; const float* A1; const float* A2;
    int k0, k1, k2;
    int bc0, bc1, bc2;
    int ldb;
    const float* Bt;
    const float* bias;
    const int* gidx; const float* gsrc;
    float* C; int M, Ntot;
    int mode;
    const int* dst; const float* Qm; float* den; float* acc; const float* ex;
    float* C1; float* C2; const float* bias1; const float* bias2;
};

#define PADK 20                       // floats per smem row (80B, 16-aligned)
#define BUF_U32 2560                  // 128*20 per stage per matrix
#define GSMEM_BYTES (6 * BUF_U32 * 4) // 3 stages x (A+B) = 61440

__global__ __launch_bounds__(256, 2) void mma_gemm(TG p) {
    extern __shared__ uint32_t sh[];   // [A0|A1|A2|B0|B1|B2] x 2560 u32
    const uint32_t sbase = smem_u32(sh);

    const int tid = threadIdx.x;
    const int lid = tid & 31, wid = tid >> 5;
    const int warp_m = wid & 3, warp_n = wid >> 2;
    const int gID = lid >> 2, tig = lid & 3;
    const int m0 = blockIdx.y * 128, n0 = blockIdx.x * 128;

    float c[2][8][4];
#pragma unroll
    for (int mt = 0; mt < 2; mt++)
#pragma unroll
        for (int nt = 0; nt < 8; nt++)
#pragma unroll
            for (int i = 0; i < 4; i++) c[mt][nt][i] = 0.f;

    const int K = p.k0 + p.k1 + p.k2;
    const int nch = K >> 4;

    auto load_chunk = [&](int kb) {
        int off = kb << 4;
        const float* A; int lda; int bc;
        if (off < p.k0)             { A = p.A0; lda = p.k0; bc = p.bc0; }
        else if (off < p.k0 + p.k1) { A = p.A1; lda = p.k1; bc = p.bc1; off -= p.k0; }
        else                        { A = p.A2; lda = p.k2; bc = p.bc2; off -= p.k0 + p.k1; }
        int st = kb % 3;
        uint32_t ab = sbase + st * (BUF_U32 * 4);
        uint32_t bb = sbase + (3 + st) * (BUF_U32 * 4);
#pragma unroll
        for (int j = 0; j < 2; j++) {
            int id = tid + j * 256;
            int row = id >> 2, kq = id & 3;
            int gm = m0 + row;
            int gmc = gm < p.M ? gm : p.M - 1;
            cp16(ab + row * 80 + kq * 16,
                 A + (size_t)gmc * lda + off + kq * 4, gm < p.M ? 16 : 0);
            cp16(bb + row * 80 + kq * 16,
                 p.Bt + (size_t)(n0 + row) * p.ldb + bc + off + kq * 4, 16);
        }
        cpa_commit();
    };

    load_chunk(0);
    load_chunk(1);

    for (int kb = 0; kb < nch; kb++) {
        if (kb + 2 < nch) load_chunk(kb + 2);
        int np = nch - kb - 1; if (np > 2) np = 2;
        if (np == 2) cpa_wait<2>();
        else if (np == 1) cpa_wait<1>();
        else cpa_wait<0>();
        __syncthreads();

        int st = kb % 3;
        const uint32_t* shA = sh + st * BUF_U32;
        const uint32_t* shB = sh + (3 + st) * BUF_U32;
#pragma unroll
        for (int k8 = 0; k8 < 16; k8 += 8) {
            uint32_t a[2][4];
#pragma unroll
            for (int mt = 0; mt < 2; mt++) {
                int rb = (warp_m * 32 + mt * 16 + gID) * PADK + k8 + tig;
                a[mt][0] = f2tf32(__uint_as_float(shA[rb]));
                a[mt][1] = f2tf32(__uint_as_float(shA[rb + 8 * PADK]));
                a[mt][2] = f2tf32(__uint_as_float(shA[rb + 4]));
                a[mt][3] = f2tf32(__uint_as_float(shA[rb + 8 * PADK + 4]));
            }
#pragma unroll
            for (int nt = 0; nt < 8; nt++) {
                int nb = (warp_n * 64 + nt * 8 + gID) * PADK + k8 + tig;
                uint32_t b0 = shB[nb], b1 = shB[nb + 4];
#pragma unroll
                for (int mt = 0; mt < 2; mt++)
                    mma1688(c[mt][nt], a[mt], b0, b1);
            }
        }
        __syncthreads();
    }

    // ---- epilogue ----
#pragma unroll
    for (int mt = 0; mt < 2; mt++) {
#pragma unroll
        for (int half = 0; half < 2; half++) {
            int gm = m0 + warp_m * 32 + mt * 16 + gID + half * 8;
            if (gm >= p.M) continue;
            if (p.mode == 0) {
                float* Cb; const float* bb; int stride; int cbase;
                if (p.C1) {
                    Cb = (blockIdx.x == 0) ? p.C : (blockIdx.x == 1 ? p.C1 : p.C2);
                    bb = (blockIdx.x == 0) ? p.bias : (blockIdx.x == 1 ? p.bias1 : p.bias2);
                    stride = HH; cbase = 0;
                } else { Cb = p.C; bb = p.bias; stride = p.Ntot; cbase = n0; }
                const float* grow = nullptr;
                if (p.gsrc) grow = p.gsrc + (size_t)p.gidx[gm] * p.Ntot;
                float* crow = Cb + (size_t)gm * stride;
#pragma unroll
                for (int nt = 0; nt < 8; nt++) {
                    int coll = warp_n * 64 + nt * 8 + tig * 2;
                    int col = cbase + coll;
                    float v0 = c[mt][nt][half * 2 + 0];
                    float v1 = c[mt][nt][half * 2 + 1];
                    if (bb)   { v0 += bb[col]; v1 += bb[col + 1]; }
                    if (grow) { v0 += grow[col]; v1 += grow[col + 1]; }
                    *(float2*)(crow + col) = make_float2(v0, v1);
                }
            } else if (p.mode == 1) {
                int d = p.dst[gm];
                const float* grow = p.gsrc + (size_t)p.gidx[gm] * HH;
                const float* qrow = p.Qm + (size_t)d * HH;
                float* crow = p.C + (size_t)gm * HH;
                float* drow = p.den + (size_t)d * HH;
#pragma unroll
                for (int nt = 0; nt < 8; nt++) {
                    int col = warp_n * 64 + nt * 8 + tig * 2;
                    float v0 = c[mt][nt][half * 2 + 0] + grow[col];
                    float v1 = c[mt][nt][half * 2 + 1] + grow[col + 1];
                    float2 q = *(const float2*)(qrow + col);
                    float e0 = expf(q.x * v0), e1 = expf(q.y * v1);
                    *(float2*)(crow + col) = make_float2(e0, e1);
                    atomicAdd(drow + col, e0);
                    atomicAdd(drow + col + 1, e1);
                }
            } else {
                int d = p.dst[gm];
                const float* grow = p.gsrc + (size_t)p.gidx[gm] * HH;
                const float* exrow = p.ex + (size_t)gm * HH;
                float* arow = p.acc + (size_t)d * HH;
#pragma unroll
                for (int nt = 0; nt < 8; nt++) {
                    int col = warp_n * 64 + nt * 8 + tig * 2;
                    float v0 = c[mt][nt][half * 2 + 0] + grow[col];
                    float v1 = c[mt][nt][half * 2 + 1] + grow[col + 1];
                    float2 e = *(const float2*)(exrow + col);
                    atomicAdd(arow + col, e.x * v0);
                    atomicAdd(arow + col + 1, e.y * v1);
                }
            }
        }
    }
}

// ---------------- fused weight transposes (one launch, tf32 pre-round) ----------
// task: Bt[n*ldb + c0 + k] = tf32(W[k*srcN + n]) for k in [0,KB), n in [0,srcN)
struct TransDesc { const float* W; float* O; int srcN; int KB; int ldb; };
struct TransParams { TransDesc t[14]; int start[15]; };

__global__ void transpose_all_k(TransParams tp) {
    __shared__ float t[32][33];
    int b = blockIdx.x;
    int i = 0;
#pragma unroll
    for (int j = 0; j < 14; j++)
        if (b >= tp.start[j + 1]) i = j + 1;
    const TransDesc d = tp.t[i];
    int rem = b - tp.start[i];
    int ntk = d.KB >> 5;
    int tx = (rem % ntk) * 32;       // k tile
    int ty = (rem / ntk) * 32;       // n tile
#pragma unroll
    for (int r = 0; r < 4; r++) {
        int k = tx + threadIdx.y + r * 8, n = ty + threadIdx.x;
        t[threadIdx.y + r * 8][threadIdx.x] = d.W[(size_t)k * d.srcN + n];
    }
    __syncthreads();
#pragma unroll
    for (int r = 0; r < 4; r++) {
        int n = ty + threadIdx.y + r * 8, k = tx + threadIdx.x;
        d.O[(size_t)n * d.ldb + k] =
            __uint_as_float(f2tf32(t[threadIdx.x][threadIdx.y + r * 8]));
    }
}

// ---------------- node div ----------------
__global__ __launch_bounds__(256) void node_div_k(
    const float* __restrict__ den, const float* __restrict__ acc,
    float* __restrict__ out)
{
    int i = blockIdx.x * 256 + threadIdx.x;
    if (i < NN * HH) {
        float d = den[i];
        out[i] = (d > 0.f) ? acc[i] / d : 0.f;
    }
}

// ---------------- layernorms ----------------
__global__ __launch_bounds__(128) void ln128_k(
    const float* __restrict__ x, const float* __restrict__ g,
    const float* __restrict__ b, float* __restrict__ y)
{
    int row = blockIdx.x, t = threadIdx.x;
    float v = x[(size_t)row * 128 + t];
    float s = v, s2 = v * v;
#pragma unroll
    for (int o = 16; o > 0; o >>= 1) {
        s  += __shfl_xor_sync(0xffffffffu, s, o);
        s2 += __shfl_xor_sync(0xffffffffu, s2, o);
    }
    __shared__ float ws[4], ws2[4];
    int w = t >> 5, l = t & 31;
    if (l == 0) { ws[w] = s; ws2[w] = s2; }
    __syncthreads();
    s  = ws[0] + ws[1] + ws[2] + ws[3];
    s2 = ws2[0] + ws2[1] + ws2[2] + ws2[3];
    float mu  = s * (1.f / 128.f);
    float var = s2 * (1.f / 128.f) - mu * mu;
    float r = rsqrtf(var + 1e-5f);
    y[(size_t)row * 128 + t] = (v - mu) * r * g[t] + b[t];
}

__global__ __launch_bounds__(256) void ln768_k(
    const float* __restrict__ x, const float* __restrict__ g,
    const float* __restrict__ b, float* __restrict__ y)
{
    int row = blockIdx.x, t = threadIdx.x;
    const float* xr = x + (size_t)row * 768;
    float v0 = xr[t], v1 = xr[t + 256], v2 = xr[t + 512];
    float s = v0 + v1 + v2;
    float s2 = v0 * v0 + v1 * v1 + v2 * v2;
#pragma unroll
    for (int o = 16; o > 0; o >>= 1) {
        s  += __shfl_xor_sync(0xffffffffu, s, o);
        s2 += __shfl_xor_sync(0xffffffffu, s2, o);
    }
    __shared__ float ws[8], ws2[8];
    int w = t >> 5, l = t & 31;
    if (l == 0) { ws[w] = s; ws2[w] = s2; }
    __syncthreads();
    s = 0.f; s2 = 0.f;
#pragma unroll
    for (int i = 0; i < 8; i++) { s += ws[i]; s2 += ws2[i]; }
    float mu  = s * (1.f / 768.f);
    float var = s2 * (1.f / 768.f) - mu * mu;
    float r = rsqrtf(var + 1e-5f);
    float* yr = y + (size_t)row * 768;
    yr[t]       = (v0 - mu) * r * g[t]       + b[t];
    yr[t + 256] = (v1 - mu) * r * g[t + 256] + b[t + 256];
    yr[t + 512] = (v2 - mu) * r * g[t + 512] + b[t + 512];
}

// ---------------- gate + pool ----------------
__global__ __launch_bounds__(256) void gate_k(
    const float* __restrict__ h1, const float* __restrict__ gw,
    const float* __restrict__ gb, float* __restrict__ gex,
    float* __restrict__ S)
{
    int w = threadIdx.x >> 5, l = threadIdx.x & 31;
    int node = blockIdx.x * 8 + w;
    float dot = 0.f;
    if (node < NN) {
        const float* hr = h1 + (size_t)node * 768;
#pragma unroll
        for (int k = 0; k < 24; k++)
            dot = fmaf(hr[l + 32 * k], gw[l + 32 * k], dot);
    }
#pragma unroll
    for (int o = 16; o > 0; o >>= 1) dot += __shfl_xor_sync(0xffffffffu, dot, o);
    __shared__ float ws[8];
    if (l == 0) {
        float ex = 0.f;
        if (node < NN) { ex = expf(dot + gb[0]); gex[node] = ex; }
        ws[w] = ex;
    }
    __syncthreads();
    if (threadIdx.x == 0) {
        float t = 0.f;
#pragma unroll
        for (int i = 0; i < 8; i++) t += ws[i];
        atomicAdd(S, t);
    }
}

__global__ __launch_bounds__(256) void pool_k(
    const float* __restrict__ h1, const float* __restrict__ gex,
    const float* __restrict__ S, float* __restrict__ out)
{
    int c = blockIdx.x * 256 + threadIdx.x;
    int nstart = blockIdx.y * 512;
    int nend = nstart + 512; if (nend > NN) nend = NN;
    float a = 0.f;
    for (int n = nstart; n < nend; n++)
        a = fmaf(gex[n], h1[(size_t)n * 768 + c], a);
    atomicAdd(&out[c], a * (1.f / S[0]));
}

// ---------------- host ----------------
static void launch_tg(const TG& p) {
    dim3 grid(p.Ntot / 128, (p.M + 127) / 128);
    mma_gemm<<<grid, 256, GSMEM_BYTES>>>(p);
}

extern "C" void kernel_launch(void* const* d_in, const int* in_sizes, int n_in,
                              void* d_out, int out_size) {
    const float* kind   = (const float*)d_in[0];
    const float* edge_h = (const float*)d_in[1];
    const int*   src    = (const int*)  d_in[2];
    const int*   dst    = (const int*)  d_in[3];
    const float* KW  = (const float*)d_in[4];  const float* Kb  = (const float*)d_in[5];
    const float* VW  = (const float*)d_in[6];  const float* Vb  = (const float*)d_in[7];
    const float* QW  = (const float*)d_in[8];  const float* Qb  = (const float*)d_in[9];
    const float* WW  = (const float*)d_in[10]; const float* Wb  = (const float*)d_in[11];
    const float* K2W = (const float*)d_in[12]; const float* K2b = (const float*)d_in[13];
    const float* V2W = (const float*)d_in[14]; const float* V2b = (const float*)d_in[15];
    const float* Q2W = (const float*)d_in[16]; const float* Q2b = (const float*)d_in[17];
    const float* W2W = (const float*)d_in[18]; const float* W2b = (const float*)d_in[19];
    const float* ln1g = (const float*)d_in[20]; const float* ln1b = (const float*)d_in[21];
    const float* ln2g = (const float*)d_in[22]; const float* ln2b = (const float*)d_in[23];
    const float* gw  = (const float*)d_in[24]; const float* gb  = (const float*)d_in[25];
    float* out = (float*)d_out;

    static float *pQ = nullptr, *pnK, *pnV, *pex, *pden, *pacc,
                 *phn, *ph, *plin, *ph1, *pgex, *pS, *pBt;
    if (!pQ) {
        cudaGetSymbolAddress((void**)&pQ,   g_Q);
        cudaGetSymbolAddress((void**)&pnK,  g_nK);
        cudaGetSymbolAddress((void**)&pnV,  g_nV);
        cudaGetSymbolAddress((void**)&pex,  g_ex);
        cudaGetSymbolAddress((void**)&pden, g_den);
        cudaGetSymbolAddress((void**)&pacc, g_acc);
        cudaGetSymbolAddress((void**)&phn,  g_hn);
        cudaGetSymbolAddress((void**)&ph,   g_h);
        cudaGetSymbolAddress((void**)&plin, g_lin);
        cudaGetSymbolAddress((void**)&ph1,  g_h1);
        cudaGetSymbolAddress((void**)&pgex, g_gex);
        cudaGetSymbolAddress((void**)&pS,   g_S);
        cudaGetSymbolAddress((void**)&pBt,  g_Bt);
        cudaFuncSetAttribute(mma_gemm, cudaFuncAttributeMaxDynamicSharedMemorySize,
                             GSMEM_BYTES);
    }

    // packed transposed-weight offsets (floats)
    const int oN1  = 0;        // [384,128]: rows 0-127 Q | 128-255 nodeK | 256-383 nodeV
    const int oKe1 = 49152;    // [128,128]: KW edge part
    const int oVe1 = 65536;    // [128,128]: VW edge part
    const int oW1  = 81920;    // [128,256]: WW full
    const int oN2  = 114688;   // [384,256]: Q2 full | K2 node(kind,h) | V2 node
    const int oKe2 = 212992;   // [128,128]: K2W edge part
    const int oVe2 = 229376;   // [128,128]: V2W edge part
    const int oW2  = 245760;   // [768,384]: W2W full

    TransParams tp;
    tp.t[0]  = {QW,                pBt + oN1,             128, 128, 128};
    tp.t[1]  = {KW,                pBt + oN1 + 128 * 128, 128, 128, 128};
    tp.t[2]  = {VW,                pBt + oN1 + 256 * 128, 128, 128, 128};
    tp.t[3]  = {KW + 128 * 128,    pBt + oKe1,            128, 128, 128};
    tp.t[4]  = {VW + 128 * 128,    pBt + oVe1,            128, 128, 128};
    tp.t[5]  = {WW,                pBt + oW1,             128, 256, 256};
    tp.t[6]  = {Q2W,               pBt + oN2,             128, 256, 256};
    tp.t[7]  = {K2W,               pBt + oN2 + 128 * 256,       128, 128, 256};
    tp.t[8]  = {K2W + 256 * 128,   pBt + oN2 + 128 * 256 + 128, 128, 128, 256};
    tp.t[9]  = {V2W,               pBt + oN2 + 256 * 256,       128, 128, 256};
    tp.t[10] = {V2W + 256 * 128,   pBt + oN2 + 256 * 256 + 128, 128, 128, 256};
    tp.t[11] = {K2W + 128 * 128,   pBt + oKe2,            128, 128, 128};
    tp.t[12] = {V2W + 128 * 128,   pBt + oVe2,            128, 128, 128};
    tp.t[13] = {W2W,               pBt + oW2,             768, 384, 384};
    int s = 0;
    for (int i = 0; i < 14; i++) {
        tp.start[i] = s;
        s += (tp.t[i].srcN >> 5) * (tp.t[i].KB >> 5);
    }
    tp.start[14] = s;
    transpose_all_k<<<s, dim3(32, 8)>>>(tp);

    const size_t nh_bytes = (size_t)NN * HH * sizeof(float);
    TG p;

    // ===================== layer 1 =====================
    cudaMemsetAsync(pden, 0, nh_bytes);
    cudaMemsetAsync(pacc, 0, nh_bytes);

    // fused node GEMM: Q | nodeK | nodeV = kind @ {QW, KW[0:F], VW[0:F]}
    p = {kind, nullptr, nullptr, FF, 0, 0, 0, 0, 0, 128, pBt + oN1,
         Qb, nullptr, nullptr, pQ, NN, 384, 0,
         nullptr, nullptr, nullptr, nullptr, nullptr,
         pnK, pnV, Kb, Vb};
    launch_tg(p);
    // eK fused: ex = exp(Q[dst] * (edge_h@KWe + nodeK[src])); den[dst]+=ex
    p = {edge_h, nullptr, nullptr, FF, 0, 0, 0, 0, 0, 128, pBt + oKe1,
         nullptr, src, pnK, pex, EE, HH, 1,
         dst, pQ, pden, nullptr, nullptr,
         nullptr, nullptr, nullptr, nullptr};
    launch_tg(p);
    // eV fused: acc[dst] += ex * (edge_h@VWe + nodeV[src])
    p = {edge_h, nullptr, nullptr, FF, 0, 0, 0, 0, 0, 128, pBt + oVe1,
         nullptr, src, pnV, nullptr, EE, HH, 2,
         dst, nullptr, nullptr, pacc, pex,
         nullptr, nullptr, nullptr, nullptr};
    launch_tg(p);

    node_div_k<<<(NN * HH + 255) / 256, 256>>>(pden, pacc, phn);

    // lin1 = concat(h_n, kind) @ WW + Wb ; h = LN(lin1)
    p = {phn, kind, nullptr, HH, FF, 0, 0, HH, 0, 256, pBt + oW1,
         Wb, nullptr, nullptr, plin, NN, HH, 0,
         nullptr, nullptr, nullptr, nullptr, nullptr,
         nullptr, nullptr, nullptr, nullptr};
    launch_tg(p);
    ln128_k<<<NN, 128>>>(plin, ln1g, ln1b, ph);

    // ===================== layer 2 =====================
    cudaMemsetAsync(pden, 0, nh_bytes);
    cudaMemsetAsync(pacc, 0, nh_bytes);

    // fused node GEMM: Q2 | nodeK2 | nodeV2 = [kind,h] @ packed
    p = {kind, ph, nullptr, FF, HH, 0, 0, 128, 0, 256, pBt + oN2,
         Q2b, nullptr, nullptr, pQ, NN, 384, 0,
         nullptr, nullptr, nullptr, nullptr, nullptr,
         pnK, pnV, K2b, V2b};
    launch_tg(p);
    // eK2 fused
    p = {edge_h, nullptr, nullptr, FF, 0, 0, 0, 0, 0, 128, pBt + oKe2,
         nullptr, src, pnK, pex, EE, HH, 1,
         dst, pQ, pden, nullptr, nullptr,
         nullptr, nullptr, nullptr, nullptr};
    launch_tg(p);
    // eV2 fused
    p = {edge_h, nullptr, nullptr, FF, 0, 0, 0, 0, 0, 128, pBt + oVe2,
         nullptr, src, pnV, nullptr, EE, HH, 2,
         dst, nullptr, nullptr, pacc, pex,
         nullptr, nullptr, nullptr, nullptr};
    launch_tg(p);

    node_div_k<<<(NN * HH + 255) / 256, 256>>>(pden, pacc, phn);

    // lin2 = concat(h_n1, h, kind) @ W2W + W2b ; h1 = LN(lin2)
    p = {phn, ph, kind, HH, HH, FF, 0, HH, 2 * HH, 384, pBt + oW2,
         W2b, nullptr, nullptr, plin, NN, OUTD, 0,
         nullptr, nullptr, nullptr, nullptr, nullptr,
         nullptr, nullptr, nullptr, nullptr};
    launch_tg(p);
    ln768_k<<<NN, 256>>>(plin, ln2g, ln2b, ph1);

    // ===================== pooling =====================
    cudaMemsetAsync(pS, 0, sizeof(float));
    cudaMemsetAsync(out, 0, (size_t)OUTD * sizeof(float));
    gate_k<<<(NN + 7) / 8, 256>>>(ph1, gw, gb, pgex, pS);
    dim3 pg(3, (NN + 511) / 512);
    pool_k<<<pg, 256>>>(ph1, pgex, pS, out);
}